// round 12
// baseline (speedup 1.0000x reference)
#include <cuda_runtime.h>
#include <cstdint>

#define VOCAB 21128
#define EMB   768
#define HID   256
#define NTAGS 8
#define BATCH 64
#define SEQ   512
#define NTOK  (BATCH * SEQ)
#define NCORP 10
#define NCHUNK 32
#define CLEN   16

#define ZROWS  21248                  // vocab padded to 332*64
#define QS     1024.0f
#define IQS2   9.5367431640625e-07f   // 1 / (1024*1024)

// ---------------- scratch (device globals; no allocs allowed) ----------------
__device__ float g_logits[NTOK * NTAGS];
__device__ float g_ctr10[NCORP * HID];
__device__ __align__(16) unsigned g_fc1i8[24 * 2048];  // fc1_w s8*1024, [ks][n][8w]
__device__ float g_Z[ZROWS * HID];
__device__ float g_crfM[BATCH * NCHUNK * 64];
__device__ int   g_flags[VOCAB];
__device__ int   g_slot[VOCAB];
__device__ int   g_wlist[ZROWS];
__device__ int   g_count;

// ---------------------------------------------------------------------------
__device__ __forceinline__ unsigned pack_s8x4(int x0, int x1, int x2, int x3) {
    unsigned t, r, z = 0;
    asm("cvt.pack.sat.s8.s32.b32 %0, %1, %2, %3;" : "=r"(t) : "r"(x3), "r"(x2), "r"(z));
    asm("cvt.pack.sat.s8.s32.b32 %0, %1, %2, %3;" : "=r"(r) : "r"(x1), "r"(x0), "r"(t));
    return r;
}
__device__ __forceinline__ int q8(float x) { return __float2int_rn(x * QS); }

__device__ __forceinline__ void imma32(int* c, const unsigned* a, unsigned b0, unsigned b1) {
    asm volatile(
        "mma.sync.aligned.m16n8k32.row.col.s32.s8.s8.s32 "
        "{%0,%1,%2,%3},{%4,%5,%6,%7},{%8,%9},{%0,%1,%2,%3};"
        : "+r"(c[0]), "+r"(c[1]), "+r"(c[2]), "+r"(c[3])
        : "r"(a[0]), "r"(a[1]), "r"(a[2]), "r"(a[3]), "r"(b0), "r"(b1));
}

// ---------------------------------------------------------------------------
// prep_all: fused weight-quant + domain-ctr + metadata zeroing.
// blocks [0,96): fc1i8; [96,106): ctr; [106,190): zero flags/wlist/count.
// ---------------------------------------------------------------------------
__global__ __launch_bounds__(256) void prep_all(
    const float* __restrict__ fc1_w,
    const float* __restrict__ dom_w,
    const float* __restrict__ fc1_b) {

    __shared__ float sDom[HID];
    const int bx = blockIdx.x, tid = threadIdx.x;

    if (bx < 96) {
        int id = bx * 256 + tid;
        int ks = id >> 10, rem = id & 1023;
        int n = rem >> 2, q = rem & 3;
        const float* src = fc1_w + n * (HID + EMB) + ks * 32 + q * 8;
        float4 v0 = *(const float4*)(src);
        float4 v1 = *(const float4*)(src + 4);
        uint2 o;
        o.x = pack_s8x4(q8(v0.x), q8(v0.y), q8(v0.z), q8(v0.w));
        o.y = pack_s8x4(q8(v1.x), q8(v1.y), q8(v1.z), q8(v1.w));
        ((uint2*)g_fc1i8)[ks * 1024 + n * 4 + q] = o;
    } else if (bx < 106) {
        const int c = bx - 96;
        sDom[tid] = dom_w[c * HID + tid];
        __syncthreads();
        const int w = tid >> 5, lane = tid & 31;
        for (int n = w; n < HID; n += 8) {
            const float* row = fc1_w + n * (HID + EMB) + EMB;
            float4 x0 = *(const float4*)(row + lane * 4);
            float4 x1 = *(const float4*)(row + 128 + lane * 4);
            float4 d0 = *(const float4*)(sDom + lane * 4);
            float4 d1 = *(const float4*)(sDom + 128 + lane * 4);
            float acc = x0.x * d0.x + x0.y * d0.y + x0.z * d0.z + x0.w * d0.w
                      + x1.x * d1.x + x1.y * d1.y + x1.z * d1.z + x1.w * d1.w;
#pragma unroll
            for (int off = 16; off > 0; off >>= 1)
                acc += __shfl_down_sync(0xffffffffu, acc, off);
            if (lane == 0) g_ctr10[c * HID + n] = acc + fc1_b[n];
        }
    } else {
        int i = (bx - 106) * 256 + tid;
        if (i < VOCAB) g_flags[i] = 0;
        if (i < ZROWS) g_wlist[i] = 0;
        if (i == 0) g_count = 0;
    }
}

// ---------------------------------------------------------------------------
// flag_compact: token-driven dedup + warp-aggregated slot assignment.
// ---------------------------------------------------------------------------
__global__ __launch_bounds__(512) void flag_compact(const int* __restrict__ words) {
    const int tid = threadIdx.x, lane = tid & 31;
    const int w = words[blockIdx.x * 512 + tid];
    const int isnew = (atomicExch(&g_flags[w], 1) == 0);
    unsigned mask = __ballot_sync(0xffffffffu, isnew);
    int n = __popc(mask);
    int base = 0;
    if (lane == 0 && n) base = atomicAdd(&g_count, n);
    base = __shfl_sync(0xffffffffu, base, 0);
    if (isnew) {
        int slot = base + __popc(mask & ((1u << lane) - 1));
        g_slot[w] = slot;
        g_wlist[slot] = w;
    }
}

// ---------------------------------------------------------------------------
// gemm_z: Z[slot, 256] = embed[wlist[slot]] @ W1emb^T via int8 IMMA.
// ---------------------------------------------------------------------------
#define GST    12
#define GSTAGE 3840
#define GBOFF  768

__global__ __launch_bounds__(256, 2) void gemm_z(const float* __restrict__ embed_w) {
    __shared__ unsigned S[2 * GSTAGE];

    const int m0 = blockIdx.x * 64;
    const int padded = (g_count + 63) & ~63;
    if (m0 >= padded) return;

    const int tid  = threadIdx.x;
    const int warp = tid >> 5, lane = tid & 31;
    const int wm = warp >> 2, wn = warp & 3;
    const int gr = lane >> 2, tc = lane & 3;

    const int aR = tid >> 2, aQ = tid & 3;
    const float* aSrc = embed_w + (long)__ldg(g_wlist + m0 + aR) * EMB + aQ * 8;
    const uint4* bSrc = (const uint4*)g_fc1i8 + tid * 2;

    const int aDst = aR * GST + aQ * 2;
    const int bDst = GBOFF + tid * GST;

    int acc[2][8][4];
#pragma unroll
    for (int mi = 0; mi < 2; mi++)
#pragma unroll
        for (int nj = 0; nj < 8; nj++)
#pragma unroll
            for (int q = 0; q < 4; q++) acc[mi][nj][q] = 0;

    float4 aV0 = *(const float4*)(aSrc);
    float4 aV1 = *(const float4*)(aSrc + 4);
    uint4  bV0 = *(bSrc);
    uint4  bV1 = *(bSrc + 1);
    {
        uint2 o;
        o.x = pack_s8x4(q8(aV0.x), q8(aV0.y), q8(aV0.z), q8(aV0.w));
        o.y = pack_s8x4(q8(aV1.x), q8(aV1.y), q8(aV1.z), q8(aV1.w));
        *(uint2*)(S + aDst) = o;
        *(uint4*)(S + bDst) = bV0;
        *(uint4*)(S + bDst + 4) = bV1;
    }
    __syncthreads();

    const int r0a = wm * 32 + gr;
    const int n0  = wn * 64 + gr;

#pragma unroll 2
    for (int it = 0; it < 24; ++it) {
        unsigned* cur = S + (it & 1) * GSTAGE;

        if (it + 1 < 24) {
            const float* ap = aSrc + (it + 1) * 32;
            aV0 = *(const float4*)(ap);
            aV1 = *(const float4*)(ap + 4);
            const uint4* bp = bSrc + (it + 1) * 512;
            bV0 = *(bp);
            bV1 = *(bp + 1);
        }

        unsigned a[2][4];
#pragma unroll
        for (int mi = 0; mi < 2; mi++) {
            int r0 = r0a + mi * 16;
            a[mi][0] = cur[r0 * GST + tc];
            a[mi][1] = cur[(r0 + 8) * GST + tc];
            a[mi][2] = cur[r0 * GST + tc + 4];
            a[mi][3] = cur[(r0 + 8) * GST + tc + 4];
        }
#pragma unroll
        for (int nj = 0; nj < 8; nj++) {
            int n = n0 + nj * 8;
            unsigned b0 = cur[GBOFF + n * GST + tc];
            unsigned b1 = cur[GBOFF + n * GST + tc + 4];
            imma32(acc[0][nj], a[0], b0, b1);
            imma32(acc[1][nj], a[1], b0, b1);
        }

        if (it + 1 < 24) {
            unsigned* nxt = S + ((it + 1) & 1) * GSTAGE;
            uint2 o;
            o.x = pack_s8x4(q8(aV0.x), q8(aV0.y), q8(aV0.z), q8(aV0.w));
            o.y = pack_s8x4(q8(aV1.x), q8(aV1.y), q8(aV1.z), q8(aV1.w));
            *(uint2*)(nxt + aDst) = o;
            *(uint4*)(nxt + bDst) = bV0;
            *(uint4*)(nxt + bDst + 4) = bV1;
        }
        __syncthreads();
    }

#pragma unroll
    for (int mi = 0; mi < 2; mi++)
#pragma unroll
        for (int half = 0; half < 2; half++) {
            int row = wm * 32 + mi * 16 + half * 8 + gr;
#pragma unroll
            for (int nj = 0; nj < 8; nj++) {
                int col = wn * 64 + nj * 8 + tc * 2;
                float2 z;
                z.x = (float)acc[mi][nj][half * 2 + 0] * IQS2;
                z.y = (float)acc[mi][nj][half * 2 + 1] * IQS2;
                *(float2*)(g_Z + (long)(m0 + row) * HID + col) = z;
            }
        }
}

// ---------------------------------------------------------------------------
// crf_tok (FUSED): per chunk of 16 tokens — gather Z, relu(+dctr), FC2,
// log_softmax, then the 16-step CRF operator-matrix scan. grid 2048, block 64.
// ---------------------------------------------------------------------------
#define HPAD 260
__global__ __launch_bounds__(64) void crf_tok(
    const int* __restrict__ words,
    const int* __restrict__ corpus,
    const float* __restrict__ trans,
    const float* __restrict__ fc2_w,
    const float* __restrict__ fc2_b) {

    __shared__ float sH[CLEN * HPAD];     // 16.6 KB  relu(Z+dctr) rows
    __shared__ float sD[HID];             // dctr for this batch elem
    __shared__ float sL[CLEN * NTAGS];    // logits of this chunk
    __shared__ int   sW[CLEN];

    const int b = blockIdx.x >> 5, chunk = blockIdx.x & 31;
    const int tid = threadIdx.x, lane = tid & 31;
    const int j = tid & 7, rowBase = lane & ~7;

    // --- w2 / fb / trans-col registers ---
    float w2[NTAGS][8];
#pragma unroll
    for (int t = 0; t < NTAGS; t++) {
        float4 u0 = __ldg((const float4*)(fc2_w + t * HID + lane * 8));
        float4 u1 = __ldg((const float4*)(fc2_w + t * HID + lane * 8 + 4));
        w2[t][0] = u0.x; w2[t][1] = u0.y; w2[t][2] = u0.z; w2[t][3] = u0.w;
        w2[t][4] = u1.x; w2[t][5] = u1.y; w2[t][6] = u1.z; w2[t][7] = u1.w;
    }
    float fb[NTAGS];
    {
        float4 u0 = __ldg((const float4*)(fc2_b));
        float4 u1 = __ldg((const float4*)(fc2_b + 4));
        fb[0] = u0.x; fb[1] = u0.y; fb[2] = u0.z; fb[3] = u0.w;
        fb[4] = u1.x; fb[5] = u1.y; fb[6] = u1.z; fb[7] = u1.w;
    }
    float tcol[8];
#pragma unroll
    for (int k = 0; k < 8; k++) tcol[k] = __ldg(trans + k * NTAGS + j);

    // --- stage dctr + chunk words ---
    const int cix = __ldg(corpus + b);
    *(float4*)&sD[tid * 4] = __ldg((const float4*)(g_ctr10 + cix * HID + tid * 4));
    if (tid < CLEN) sW[tid] = words[b * SEQ + chunk * CLEN + tid];
    __syncthreads();

    // --- gather h = relu(Z[slot] + dctr): thread = (token tid>>2, 64-col seg tid&3)
    {
        const int tok = tid >> 2, q = tid & 3;
        const int slot = __ldg(g_slot + sW[tok]);
        const float* zr = g_Z + (long)slot * HID + q * 64;
        const float* dp = sD + q * 64;
        float* hp = sH + tok * HPAD + q * 64;
#pragma unroll
        for (int i = 0; i < 16; i++) {
            float4 z = __ldg((const float4*)(zr + i * 4));
            float4 h;
            h.x = fmaxf(z.x + dp[i * 4 + 0], 0.f);
            h.y = fmaxf(z.y + dp[i * 4 + 1], 0.f);
            h.z = fmaxf(z.z + dp[i * 4 + 2], 0.f);
            h.w = fmaxf(z.w + dp[i * 4 + 3], 0.f);
            *(float4*)(hp + i * 4) = h;
        }
    }
    __syncthreads();

    // --- FC2 + log_softmax: warp (tid>>5) handles tokens w*8..w*8+7 ---
    const int w0 = (tid >> 5) * 8;
    for (int k = 0; k < 8; k++) {
        const int tok = w0 + k;
        float4 h0 = *(const float4*)&sH[tok * HPAD + lane * 8];
        float4 h1 = *(const float4*)&sH[tok * HPAD + lane * 8 + 4];
        float hx[8] = {h0.x, h0.y, h0.z, h0.w, h1.x, h1.y, h1.z, h1.w};
        float p[NTAGS];
#pragma unroll
        for (int t = 0; t < NTAGS; t++) {
            float s = 0.f;
#pragma unroll
            for (int q = 0; q < 8; q++) s = fmaf(hx[q], w2[t][q], s);
            p[t] = s;
        }
#pragma unroll
        for (int off = 16; off > 0; off >>= 1)
#pragma unroll
            for (int t = 0; t < NTAGS; t++)
                p[t] += __shfl_xor_sync(0xffffffffu, p[t], off);

        if (lane == 0) {
            float mx = -1e30f;
#pragma unroll
            for (int t = 0; t < NTAGS; t++) { p[t] += fb[t]; mx = fmaxf(mx, p[t]); }
            float sm = 0.f;
#pragma unroll
            for (int t = 0; t < NTAGS; t++) sm += __expf(p[t] - mx);
            float lse = mx + __logf(sm);
            float* o = g_logits + (long)(b * SEQ + chunk * CLEN + tok) * NTAGS;
#pragma unroll
            for (int t = 0; t < NTAGS; t++) {
                float lg = p[t] - lse;
                sL[tok * NTAGS + t] = lg;
                o[t] = lg;
            }
        }
    }
    __syncthreads();

    // --- 16-step operator-matrix scan ---
    float M = ((tid >> 3) == j) ? 0.f : -1e30f;
    const int skip0 = (chunk == 0);

#pragma unroll
    for (int s = 0; s < CLEN; s++) {
        float emit = sL[s * NTAGS + j];
        int live = (sW[s] != 0) & ((s > 0) | !skip0);
        float v[8];
#pragma unroll
        for (int k = 0; k < 8; k++)
            v[k] = __shfl_sync(0xffffffffu, M, rowBase + k) + tcol[k];
        float m01 = fmaxf(v[0], v[1]), m23 = fmaxf(v[2], v[3]);
        float m45 = fmaxf(v[4], v[5]), m67 = fmaxf(v[6], v[7]);
        float mx  = fmaxf(fmaxf(m01, m23), fmaxf(m45, m67));
        float s0 = __expf(v[0] - mx) + __expf(v[1] - mx);
        float s1 = __expf(v[2] - mx) + __expf(v[3] - mx);
        float s2 = __expf(v[4] - mx) + __expf(v[5] - mx);
        float s3 = __expf(v[6] - mx) + __expf(v[7] - mx);
        float nv = mx + __logf((s0 + s1) + (s2 + s3)) + emit;
        M = live ? nv : M;
    }
    g_crfM[blockIdx.x * 64 + tid] = M;
}

// ---------------------------------------------------------------------------
// crf_fin: combine 32 chunk matrices + norm + gold score. grid 64, block 512.
// ---------------------------------------------------------------------------
__global__ __launch_bounds__(512) void crf_fin(
    const int* __restrict__ words,
    const int* __restrict__ target,
    const float* __restrict__ trans,
    const float* __restrict__ start_s,
    const float* __restrict__ end_s,
    float* __restrict__ out) {

    __shared__ float sM[NCHUNK * 64];
    __shared__ float sRed[16];
    __shared__ int   sRedI[16];
    __shared__ float sNorm;

    const int b = blockIdx.x, tid = threadIdx.x;
    const int lane = tid & 31;
    const float* L = g_logits + b * SEQ * NTAGS;
    const int* wds = words + b * SEQ;
    const int* tg  = target + b * SEQ;

#pragma unroll
    for (int k = 0; k < 4; k++) sM[tid + k * 512] = g_crfM[b * (NCHUNK * 64) + tid + k * 512];
    __syncthreads();

    if (tid < 8) {
        float alpha = __ldg(L + tid) + __ldg(start_s + tid);
#pragma unroll
        for (int c = 0; c < NCHUNK; c++) {
            float v[8];
#pragma unroll
            for (int k = 0; k < 8; k++)
                v[k] = __shfl_sync(0xffu, alpha, k) + sM[c * 64 + k * 8 + tid];
            float m01 = fmaxf(v[0], v[1]), m23 = fmaxf(v[2], v[3]);
            float m45 = fmaxf(v[4], v[5]), m67 = fmaxf(v[6], v[7]);
            float mx  = fmaxf(fmaxf(m01, m23), fmaxf(m45, m67));
            float sm = __expf(v[0] - mx) + __expf(v[1] - mx) + __expf(v[2] - mx)
                     + __expf(v[3] - mx) + __expf(v[4] - mx) + __expf(v[5] - mx)
                     + __expf(v[6] - mx) + __expf(v[7] - mx);
            alpha = mx + __logf(sm);
        }
        float v = alpha + __ldg(end_s + tid);
        float mx = v;
        mx = fmaxf(mx, __shfl_xor_sync(0xffu, mx, 1));
        mx = fmaxf(mx, __shfl_xor_sync(0xffu, mx, 2));
        mx = fmaxf(mx, __shfl_xor_sync(0xffu, mx, 4));
        float sm = __expf(v - mx);
        sm += __shfl_xor_sync(0xffu, sm, 1);
        sm += __shfl_xor_sync(0xffu, sm, 2);
        sm += __shfl_xor_sync(0xffu, sm, 4);
        if (tid == 0) sNorm = mx + __logf(sm);
    }

    {
        const int s = tid;
        int m = (wds[s] != 0);
        int t = tg[s];
        float e  = m ? __ldg(L + s * NTAGS + t) : 0.f;
        float tr = (m && s > 0) ? __ldg(trans + tg[s - 1] * NTAGS + t) : 0.f;
        float val = e + tr;
        int cnt = m;
#pragma unroll
        for (int off = 16; off > 0; off >>= 1) {
            val += __shfl_down_sync(0xffffffffu, val, off);
            cnt += __shfl_down_sync(0xffffffffu, cnt, off);
        }
        if (lane == 0) { sRed[tid >> 5] = val; sRedI[tid >> 5] = cnt; }
    }
    __syncthreads();
    if (tid == 0) {
        float sum = 0.f; int c = 0;
#pragma unroll
        for (int w = 0; w < 16; w++) { sum += sRed[w]; c += sRedI[w]; }
        int last = c - 1;
        float score = sum + __ldg(start_s + tg[0]) + __ldg(end_s + tg[last]);
        out[b] = sNorm - score;
    }
}

// ---------------------------------------------------------------------------
extern "C" void kernel_launch(void* const* d_in, const int* in_sizes, int n_in,
                              void* d_out, int out_size) {
    const int*   words   = (const int*)  d_in[0];
    const int*   target  = (const int*)  d_in[1];
    const int*   corpus  = (const int*)  d_in[2];
    const float* embed_w = (const float*)d_in[3];
    const float* dom_w   = (const float*)d_in[4];
    const float* fc1_w   = (const float*)d_in[5];
    const float* fc1_b   = (const float*)d_in[6];
    const float* fc2_w   = (const float*)d_in[7];
    const float* fc2_b   = (const float*)d_in[8];
    const float* trans   = (const float*)d_in[9];
    const float* start_s = (const float*)d_in[10];
    const float* end_s   = (const float*)d_in[11];
    float* out = (float*)d_out;

    prep_all<<<190, 256>>>(fc1_w, dom_w, fc1_b);
    flag_compact<<<64, 512>>>(words);
    gemm_z<<<332, 256>>>(embed_w);
    crf_tok<<<BATCH * NCHUNK, 64>>>(words, corpus, trans, fc2_w, fc2_b);
    crf_fin<<<BATCH, 512>>>(words, target, trans, start_s, end_s, out);
}

// round 13
// speedup vs baseline: 1.1416x; 1.1416x over previous
#include <cuda_runtime.h>
#include <cstdint>

#define VOCAB 21128
#define EMB   768
#define HID   256
#define NTAGS 8
#define BATCH 64
#define SEQ   512
#define NTOK  (BATCH * SEQ)
#define NCORP 10
#define NCHUNK 32
#define CLEN   16

#define ZROWS  21248                  // vocab padded to 332*64
#define QS     1024.0f
#define IQS2   9.5367431640625e-07f   // 1 / (1024*1024)

// ---------------- scratch (device globals; no allocs allowed) ----------------
__device__ float g_logits[NTOK * NTAGS];
__device__ float g_ctr10[NCORP * HID];
__device__ __align__(16) unsigned g_fc1i8[24 * 2048];  // fc1_w s8*1024, [ks][n][8w]
__device__ float g_Z[ZROWS * HID];
__device__ float g_crfM[BATCH * NCHUNK * 64];
__device__ int   g_flags[VOCAB];
__device__ int   g_slot[VOCAB];
__device__ int   g_wlist[ZROWS];
__device__ int   g_count;

// ---------------------------------------------------------------------------
__device__ __forceinline__ unsigned pack_s8x4(int x0, int x1, int x2, int x3) {
    unsigned t, r, z = 0;
    asm("cvt.pack.sat.s8.s32.b32 %0, %1, %2, %3;" : "=r"(t) : "r"(x3), "r"(x2), "r"(z));
    asm("cvt.pack.sat.s8.s32.b32 %0, %1, %2, %3;" : "=r"(r) : "r"(x1), "r"(x0), "r"(t));
    return r;
}
__device__ __forceinline__ int q8(float x) { return __float2int_rn(x * QS); }

__device__ __forceinline__ void imma32(int* c, const unsigned* a, unsigned b0, unsigned b1) {
    asm volatile(
        "mma.sync.aligned.m16n8k32.row.col.s32.s8.s8.s32 "
        "{%0,%1,%2,%3},{%4,%5,%6,%7},{%8,%9},{%0,%1,%2,%3};"
        : "+r"(c[0]), "+r"(c[1]), "+r"(c[2]), "+r"(c[3])
        : "r"(a[0]), "r"(a[1]), "r"(a[2]), "r"(a[3]), "r"(b0), "r"(b1));
}

// ---------------------------------------------------------------------------
// prep_all: fused weight-quant + domain-ctr + metadata zeroing.
// blocks [0,96): fc1i8; [96,106): ctr; [106,190): zero flags/wlist/count.
// ---------------------------------------------------------------------------
__global__ __launch_bounds__(256) void prep_all(
    const float* __restrict__ fc1_w,
    const float* __restrict__ dom_w,
    const float* __restrict__ fc1_b) {

    __shared__ float sDom[HID];
    const int bx = blockIdx.x, tid = threadIdx.x;

    if (bx < 96) {
        int id = bx * 256 + tid;
        int ks = id >> 10, rem = id & 1023;
        int n = rem >> 2, q = rem & 3;
        const float* src = fc1_w + n * (HID + EMB) + ks * 32 + q * 8;
        float4 v0 = *(const float4*)(src);
        float4 v1 = *(const float4*)(src + 4);
        uint2 o;
        o.x = pack_s8x4(q8(v0.x), q8(v0.y), q8(v0.z), q8(v0.w));
        o.y = pack_s8x4(q8(v1.x), q8(v1.y), q8(v1.z), q8(v1.w));
        ((uint2*)g_fc1i8)[ks * 1024 + n * 4 + q] = o;
    } else if (bx < 106) {
        const int c = bx - 96;
        sDom[tid] = dom_w[c * HID + tid];
        __syncthreads();
        const int w = tid >> 5, lane = tid & 31;
        for (int n = w; n < HID; n += 8) {
            const float* row = fc1_w + n * (HID + EMB) + EMB;
            float4 x0 = *(const float4*)(row + lane * 4);
            float4 x1 = *(const float4*)(row + 128 + lane * 4);
            float4 d0 = *(const float4*)(sDom + lane * 4);
            float4 d1 = *(const float4*)(sDom + 128 + lane * 4);
            float acc = x0.x * d0.x + x0.y * d0.y + x0.z * d0.z + x0.w * d0.w
                      + x1.x * d1.x + x1.y * d1.y + x1.z * d1.z + x1.w * d1.w;
#pragma unroll
            for (int off = 16; off > 0; off >>= 1)
                acc += __shfl_down_sync(0xffffffffu, acc, off);
            if (lane == 0) g_ctr10[c * HID + n] = acc + fc1_b[n];
        }
    } else {
        int i = (bx - 106) * 256 + tid;
        if (i < VOCAB) g_flags[i] = 0;
        if (i < ZROWS) g_wlist[i] = 0;
        if (i == 0) g_count = 0;
    }
}

// ---------------------------------------------------------------------------
// flag_compact: token-driven dedup + warp-aggregated slot assignment.
// ---------------------------------------------------------------------------
__global__ __launch_bounds__(512) void flag_compact(const int* __restrict__ words) {
    const int tid = threadIdx.x, lane = tid & 31;
    const int w = words[blockIdx.x * 512 + tid];
    const int isnew = (atomicExch(&g_flags[w], 1) == 0);
    unsigned mask = __ballot_sync(0xffffffffu, isnew);
    int n = __popc(mask);
    int base = 0;
    if (lane == 0 && n) base = atomicAdd(&g_count, n);
    base = __shfl_sync(0xffffffffu, base, 0);
    if (isnew) {
        int slot = base + __popc(mask & ((1u << lane) - 1));
        g_slot[w] = slot;
        g_wlist[slot] = w;
    }
}

// ---------------------------------------------------------------------------
// gemm_z: Z[slot, 256] = embed[wlist[slot]] @ W1emb^T via int8 IMMA.
// ---------------------------------------------------------------------------
#define GST    12
#define GSTAGE 3840
#define GBOFF  768

__global__ __launch_bounds__(256, 2) void gemm_z(const float* __restrict__ embed_w) {
    __shared__ unsigned S[2 * GSTAGE];

    const int m0 = blockIdx.x * 64;
    const int padded = (g_count + 63) & ~63;
    if (m0 >= padded) return;

    const int tid  = threadIdx.x;
    const int warp = tid >> 5, lane = tid & 31;
    const int wm = warp >> 2, wn = warp & 3;
    const int gr = lane >> 2, tc = lane & 3;

    const int aR = tid >> 2, aQ = tid & 3;
    const float* aSrc = embed_w + (long)__ldg(g_wlist + m0 + aR) * EMB + aQ * 8;
    const uint4* bSrc = (const uint4*)g_fc1i8 + tid * 2;

    const int aDst = aR * GST + aQ * 2;
    const int bDst = GBOFF + tid * GST;

    int acc[2][8][4];
#pragma unroll
    for (int mi = 0; mi < 2; mi++)
#pragma unroll
        for (int nj = 0; nj < 8; nj++)
#pragma unroll
            for (int q = 0; q < 4; q++) acc[mi][nj][q] = 0;

    float4 aV0 = *(const float4*)(aSrc);
    float4 aV1 = *(const float4*)(aSrc + 4);
    uint4  bV0 = *(bSrc);
    uint4  bV1 = *(bSrc + 1);
    {
        uint2 o;
        o.x = pack_s8x4(q8(aV0.x), q8(aV0.y), q8(aV0.z), q8(aV0.w));
        o.y = pack_s8x4(q8(aV1.x), q8(aV1.y), q8(aV1.z), q8(aV1.w));
        *(uint2*)(S + aDst) = o;
        *(uint4*)(S + bDst) = bV0;
        *(uint4*)(S + bDst + 4) = bV1;
    }
    __syncthreads();

    const int r0a = wm * 32 + gr;
    const int n0  = wn * 64 + gr;

#pragma unroll 2
    for (int it = 0; it < 24; ++it) {
        unsigned* cur = S + (it & 1) * GSTAGE;

        if (it + 1 < 24) {
            const float* ap = aSrc + (it + 1) * 32;
            aV0 = *(const float4*)(ap);
            aV1 = *(const float4*)(ap + 4);
            const uint4* bp = bSrc + (it + 1) * 512;
            bV0 = *(bp);
            bV1 = *(bp + 1);
        }

        unsigned a[2][4];
#pragma unroll
        for (int mi = 0; mi < 2; mi++) {
            int r0 = r0a + mi * 16;
            a[mi][0] = cur[r0 * GST + tc];
            a[mi][1] = cur[(r0 + 8) * GST + tc];
            a[mi][2] = cur[r0 * GST + tc + 4];
            a[mi][3] = cur[(r0 + 8) * GST + tc + 4];
        }
#pragma unroll
        for (int nj = 0; nj < 8; nj++) {
            int n = n0 + nj * 8;
            unsigned b0 = cur[GBOFF + n * GST + tc];
            unsigned b1 = cur[GBOFF + n * GST + tc + 4];
            imma32(acc[0][nj], a[0], b0, b1);
            imma32(acc[1][nj], a[1], b0, b1);
        }

        if (it + 1 < 24) {
            unsigned* nxt = S + ((it + 1) & 1) * GSTAGE;
            uint2 o;
            o.x = pack_s8x4(q8(aV0.x), q8(aV0.y), q8(aV0.z), q8(aV0.w));
            o.y = pack_s8x4(q8(aV1.x), q8(aV1.y), q8(aV1.z), q8(aV1.w));
            *(uint2*)(nxt + aDst) = o;
            *(uint4*)(nxt + bDst) = bV0;
            *(uint4*)(nxt + bDst + 4) = bV1;
        }
        __syncthreads();
    }

#pragma unroll
    for (int mi = 0; mi < 2; mi++)
#pragma unroll
        for (int half = 0; half < 2; half++) {
            int row = wm * 32 + mi * 16 + half * 8 + gr;
#pragma unroll
            for (int nj = 0; nj < 8; nj++) {
                int col = wn * 64 + nj * 8 + tc * 2;
                float2 z;
                z.x = (float)acc[mi][nj][half * 2 + 0] * IQS2;
                z.y = (float)acc[mi][nj][half * 2 + 1] * IQS2;
                *(float2*)(g_Z + (long)(m0 + row) * HID + col) = z;
            }
        }
}

// ---------------------------------------------------------------------------
// tok_kernel v2: thread-per-(token,tag). grid 1024, block 256 = 32 tok x 8 tag.
// Phase 1: stage relu(Z[slot]+dctr) for 32 tokens + w2 into smem
//          (interleaved cols -> conflict-free stores; coalesced Z reads).
// Phase 2: each thread dots 256 cols (h rows broadcast across 8 lanes,
//          w2 rows across 4 -- conflict-free), 3-level shfl softmax.
// ---------------------------------------------------------------------------
#define HPAD 260
__global__ __launch_bounds__(256) void tok_kernel(
    const int* __restrict__ words,
    const int* __restrict__ corpus,
    const float* __restrict__ fc2_w,
    const float* __restrict__ fc2_b) {

    __shared__ float sH[32 * HPAD];       // 33.3 KB
    __shared__ float sW2[NTAGS * HPAD];   // 8.3 KB
    __shared__ float sD[HID];
    __shared__ int   sSlot[32];

    const int tid  = threadIdx.x;
    const int tok0 = blockIdx.x * 32;     // 32 tokens, same batch elem (512%32==0)
    const int b    = tok0 >> 9;

    if (tid < 64) {
        const int cix = __ldg(corpus + b);
        *(float4*)&sD[tid * 4] = __ldg((const float4*)(g_ctr10 + cix * HID + tid * 4));
    }
    if (tid < 32) sSlot[tid] = __ldg(g_slot + __ldg(words + tok0 + tid));
    // w2 -> smem, padded rows
    {
        int t = tid >> 5, c4 = (tid & 31);      // 8 rows x 32 float4-chunks... 256 threads cover 8*32
        float4 v = __ldg((const float4*)(fc2_w + t * HID + c4 * 8));
        float4 v2 = __ldg((const float4*)(fc2_w + t * HID + c4 * 8 + 4));
        *(float4*)&sW2[t * HPAD + c4 * 8] = v;
        *(float4*)&sW2[t * HPAD + c4 * 8 + 4] = v2;
    }
    __syncthreads();

    // Phase 1: gather h. thread = (token r = tid>>3, q = tid&7); cols q*4 + i*32
    {
        const int r = tid >> 3, q = tid & 7;
        const float* zr = g_Z + (long)sSlot[r] * HID;
        float* hp = sH + r * HPAD;
#pragma unroll
        for (int i = 0; i < 8; i++) {
            const int c = q * 4 + i * 32;
            float4 z = __ldg((const float4*)(zr + c));
            float4 h;
            h.x = fmaxf(z.x + sD[c + 0], 0.f);
            h.y = fmaxf(z.y + sD[c + 1], 0.f);
            h.z = fmaxf(z.z + sD[c + 2], 0.f);
            h.w = fmaxf(z.w + sD[c + 3], 0.f);
            *(float4*)(hp + c) = h;
        }
    }
    __syncthreads();

    // Phase 2: FC2 dot per (token r, tag t)
    const int r = tid >> 3, t = tid & 7;
    const float4* hv = (const float4*)(sH + r * HPAD);
    const float4* wv = (const float4*)(sW2 + t * HPAD);
    float p = __ldg(fc2_b + t);
#pragma unroll 8
    for (int k4 = 0; k4 < 64; k4++) {
        float4 h4 = hv[k4], w4 = wv[k4];
        p = fmaf(h4.x, w4.x, p); p = fmaf(h4.y, w4.y, p);
        p = fmaf(h4.z, w4.z, p); p = fmaf(h4.w, w4.w, p);
    }
    // softmax across the token's 8 lanes (consecutive lanes, xor 1/2/4 stays in-group)
    float mx = p;
    mx = fmaxf(mx, __shfl_xor_sync(0xffffffffu, mx, 1));
    mx = fmaxf(mx, __shfl_xor_sync(0xffffffffu, mx, 2));
    mx = fmaxf(mx, __shfl_xor_sync(0xffffffffu, mx, 4));
    float sm = __expf(p - mx);
    sm += __shfl_xor_sync(0xffffffffu, sm, 1);
    sm += __shfl_xor_sync(0xffffffffu, sm, 2);
    sm += __shfl_xor_sync(0xffffffffu, sm, 4);
    float lse = mx + __logf(sm);
    g_logits[(long)(tok0 + r) * NTAGS + t] = p - lse;
}

// ---------------------------------------------------------------------------
// crf_chunk: CLEN=16-step operator matrix per block. grid 2048, block 64.
// ---------------------------------------------------------------------------
__global__ __launch_bounds__(64) void crf_chunk(
    const int* __restrict__ words,
    const float* __restrict__ trans) {

    __shared__ float sL[CLEN * NTAGS];
    __shared__ int   sW[CLEN];

    const int b = blockIdx.x >> 5, chunk = blockIdx.x & 31;
    const int tid = threadIdx.x;
    const int j = tid & 7;
    const int lane = tid & 31, rowBase = lane & ~7;

    const float* L = g_logits + b * SEQ * NTAGS + chunk * CLEN * NTAGS;
    const int* wds = words + b * SEQ + chunk * CLEN;

    if (tid < 32) *(float4*)&sL[tid * 4] = *(const float4*)(L + tid * 4);
    if (tid < CLEN) sW[tid] = wds[tid];

    float tcol[8];
#pragma unroll
    for (int k = 0; k < 8; k++) tcol[k] = __ldg(trans + k * NTAGS + j);

    __syncthreads();

    float M = ((tid >> 3) == j) ? 0.f : -1e30f;
    const int skip0 = (chunk == 0);

#pragma unroll
    for (int s = 0; s < CLEN; s++) {
        float emit = sL[s * NTAGS + j];
        int live = (sW[s] != 0) & ((s > 0) | !skip0);
        float v[8];
#pragma unroll
        for (int k = 0; k < 8; k++)
            v[k] = __shfl_sync(0xffffffffu, M, rowBase + k) + tcol[k];
        float m01 = fmaxf(v[0], v[1]), m23 = fmaxf(v[2], v[3]);
        float m45 = fmaxf(v[4], v[5]), m67 = fmaxf(v[6], v[7]);
        float mx  = fmaxf(fmaxf(m01, m23), fmaxf(m45, m67));
        float s0 = __expf(v[0] - mx) + __expf(v[1] - mx);
        float s1 = __expf(v[2] - mx) + __expf(v[3] - mx);
        float s2 = __expf(v[4] - mx) + __expf(v[5] - mx);
        float s3 = __expf(v[6] - mx) + __expf(v[7] - mx);
        float nv = mx + __logf((s0 + s1) + (s2 + s3)) + emit;
        M = live ? nv : M;
    }
    g_crfM[blockIdx.x * 64 + tid] = M;
}

// ---------------------------------------------------------------------------
// crf_fin: combine 32 chunk matrices + norm + gold score. grid 64, block 512.
// ---------------------------------------------------------------------------
__global__ __launch_bounds__(512) void crf_fin(
    const int* __restrict__ words,
    const int* __restrict__ target,
    const float* __restrict__ trans,
    const float* __restrict__ start_s,
    const float* __restrict__ end_s,
    float* __restrict__ out) {

    __shared__ float sM[NCHUNK * 64];
    __shared__ float sRed[16];
    __shared__ int   sRedI[16];
    __shared__ float sNorm;

    const int b = blockIdx.x, tid = threadIdx.x;
    const int lane = tid & 31;
    const float* L = g_logits + b * SEQ * NTAGS;
    const int* wds = words + b * SEQ;
    const int* tg  = target + b * SEQ;

#pragma unroll
    for (int k = 0; k < 4; k++) sM[tid + k * 512] = g_crfM[b * (NCHUNK * 64) + tid + k * 512];
    __syncthreads();

    if (tid < 8) {
        float alpha = __ldg(L + tid) + __ldg(start_s + tid);
#pragma unroll
        for (int c = 0; c < NCHUNK; c++) {
            float v[8];
#pragma unroll
            for (int k = 0; k < 8; k++)
                v[k] = __shfl_sync(0xffu, alpha, k) + sM[c * 64 + k * 8 + tid];
            float m01 = fmaxf(v[0], v[1]), m23 = fmaxf(v[2], v[3]);
            float m45 = fmaxf(v[4], v[5]), m67 = fmaxf(v[6], v[7]);
            float mx  = fmaxf(fmaxf(m01, m23), fmaxf(m45, m67));
            float sm = __expf(v[0] - mx) + __expf(v[1] - mx) + __expf(v[2] - mx)
                     + __expf(v[3] - mx) + __expf(v[4] - mx) + __expf(v[5] - mx)
                     + __expf(v[6] - mx) + __expf(v[7] - mx);
            alpha = mx + __logf(sm);
        }
        float v = alpha + __ldg(end_s + tid);
        float mx = v;
        mx = fmaxf(mx, __shfl_xor_sync(0xffu, mx, 1));
        mx = fmaxf(mx, __shfl_xor_sync(0xffu, mx, 2));
        mx = fmaxf(mx, __shfl_xor_sync(0xffu, mx, 4));
        float sm = __expf(v - mx);
        sm += __shfl_xor_sync(0xffu, sm, 1);
        sm += __shfl_xor_sync(0xffu, sm, 2);
        sm += __shfl_xor_sync(0xffu, sm, 4);
        if (tid == 0) sNorm = mx + __logf(sm);
    }

    {
        const int s = tid;
        int m = (wds[s] != 0);
        int t = tg[s];
        float e  = m ? __ldg(L + s * NTAGS + t) : 0.f;
        float tr = (m && s > 0) ? __ldg(trans + tg[s - 1] * NTAGS + t) : 0.f;
        float val = e + tr;
        int cnt = m;
#pragma unroll
        for (int off = 16; off > 0; off >>= 1) {
            val += __shfl_down_sync(0xffffffffu, val, off);
            cnt += __shfl_down_sync(0xffffffffu, cnt, off);
        }
        if (lane == 0) { sRed[tid >> 5] = val; sRedI[tid >> 5] = cnt; }
    }
    __syncthreads();
    if (tid == 0) {
        float sum = 0.f; int c = 0;
#pragma unroll
        for (int w = 0; w < 16; w++) { sum += sRed[w]; c += sRedI[w]; }
        int last = c - 1;
        float score = sum + __ldg(start_s + tg[0]) + __ldg(end_s + tg[last]);
        out[b] = sNorm - score;
    }
}

// ---------------------------------------------------------------------------
extern "C" void kernel_launch(void* const* d_in, const int* in_sizes, int n_in,
                              void* d_out, int out_size) {
    const int*   words   = (const int*)  d_in[0];
    const int*   target  = (const int*)  d_in[1];
    const int*   corpus  = (const int*)  d_in[2];
    const float* embed_w = (const float*)d_in[3];
    const float* dom_w   = (const float*)d_in[4];
    const float* fc1_w   = (const float*)d_in[5];
    const float* fc1_b   = (const float*)d_in[6];
    const float* fc2_w   = (const float*)d_in[7];
    const float* fc2_b   = (const float*)d_in[8];
    const float* trans   = (const float*)d_in[9];
    const float* start_s = (const float*)d_in[10];
    const float* end_s   = (const float*)d_in[11];
    float* out = (float*)d_out;

    prep_all<<<190, 256>>>(fc1_w, dom_w, fc1_b);
    flag_compact<<<64, 512>>>(words);
    gemm_z<<<332, 256>>>(embed_w);
    tok_kernel<<<1024, 256>>>(words, corpus, fc2_w, fc2_b);
    crf_chunk<<<BATCH * NCHUNK, 64>>>(words, trans);
    crf_fin<<<BATCH, 512>>>(words, target, trans, start_s, end_s, out);
}

// round 14
// speedup vs baseline: 1.1695x; 1.0244x over previous
#include <cuda_runtime.h>
#include <cstdint>

#define VOCAB 21128
#define EMB   768
#define HID   256
#define NTAGS 8
#define BATCH 64
#define SEQ   512
#define NTOK  (BATCH * SEQ)
#define NCORP 10
#define NCHUNK 32
#define CLEN   16

#define ZROWS  21248                  // vocab padded to 332*64
#define QS     1024.0f
#define IQS2   9.5367431640625e-07f   // 1 / (1024*1024)

// ---------------- scratch (device globals; no allocs allowed) ----------------
__device__ float g_logits[NTOK * NTAGS];
__device__ float g_ctr10[NCORP * HID];
__device__ __align__(16) unsigned g_fc1i8[24 * 2048];  // fc1_w s8*1024, [ks][n][8w]
__device__ float g_Z[ZROWS * HID];
__device__ float g_crfM[BATCH * NCHUNK * 64];
__device__ int   g_flags[VOCAB];
__device__ int   g_slot[VOCAB];
__device__ int   g_wlist[ZROWS];
__device__ int   g_count;

// ---------------------------------------------------------------------------
__device__ __forceinline__ unsigned pack_s8x4(int x0, int x1, int x2, int x3) {
    unsigned t, r, z = 0;
    asm("cvt.pack.sat.s8.s32.b32 %0, %1, %2, %3;" : "=r"(t) : "r"(x3), "r"(x2), "r"(z));
    asm("cvt.pack.sat.s8.s32.b32 %0, %1, %2, %3;" : "=r"(r) : "r"(x1), "r"(x0), "r"(t));
    return r;
}
__device__ __forceinline__ int q8(float x) { return __float2int_rn(x * QS); }

__device__ __forceinline__ void imma32(int* c, const unsigned* a, unsigned b0, unsigned b1) {
    asm volatile(
        "mma.sync.aligned.m16n8k32.row.col.s32.s8.s8.s32 "
        "{%0,%1,%2,%3},{%4,%5,%6,%7},{%8,%9},{%0,%1,%2,%3};"
        : "+r"(c[0]), "+r"(c[1]), "+r"(c[2]), "+r"(c[3])
        : "r"(a[0]), "r"(a[1]), "r"(a[2]), "r"(a[3]), "r"(b0), "r"(b1));
}

// ---------------------------------------------------------------------------
// prep_all: fused weight-quant + domain-ctr + metadata zeroing.
// blocks [0,96): fc1i8; [96,106): ctr; [106,190): zero flags/wlist/count.
// ---------------------------------------------------------------------------
__global__ __launch_bounds__(256) void prep_all(
    const float* __restrict__ fc1_w,
    const float* __restrict__ dom_w,
    const float* __restrict__ fc1_b) {

    __shared__ float sDom[HID];
    const int bx = blockIdx.x, tid = threadIdx.x;

    if (bx < 96) {
        int id = bx * 256 + tid;
        int ks = id >> 10, rem = id & 1023;
        int n = rem >> 2, q = rem & 3;
        const float* src = fc1_w + n * (HID + EMB) + ks * 32 + q * 8;
        float4 v0 = *(const float4*)(src);
        float4 v1 = *(const float4*)(src + 4);
        uint2 o;
        o.x = pack_s8x4(q8(v0.x), q8(v0.y), q8(v0.z), q8(v0.w));
        o.y = pack_s8x4(q8(v1.x), q8(v1.y), q8(v1.z), q8(v1.w));
        ((uint2*)g_fc1i8)[ks * 1024 + n * 4 + q] = o;
    } else if (bx < 106) {
        const int c = bx - 96;
        sDom[tid] = dom_w[c * HID + tid];
        __syncthreads();
        const int w = tid >> 5, lane = tid & 31;
        for (int n = w; n < HID; n += 8) {
            const float* row = fc1_w + n * (HID + EMB) + EMB;
            float4 x0 = *(const float4*)(row + lane * 4);
            float4 x1 = *(const float4*)(row + 128 + lane * 4);
            float4 d0 = *(const float4*)(sDom + lane * 4);
            float4 d1 = *(const float4*)(sDom + 128 + lane * 4);
            float acc = x0.x * d0.x + x0.y * d0.y + x0.z * d0.z + x0.w * d0.w
                      + x1.x * d1.x + x1.y * d1.y + x1.z * d1.z + x1.w * d1.w;
#pragma unroll
            for (int off = 16; off > 0; off >>= 1)
                acc += __shfl_down_sync(0xffffffffu, acc, off);
            if (lane == 0) g_ctr10[c * HID + n] = acc + fc1_b[n];
        }
    } else {
        int i = (bx - 106) * 256 + tid;
        if (i < VOCAB) g_flags[i] = 0;
        if (i < ZROWS) g_wlist[i] = 0;
        if (i == 0) g_count = 0;
    }
}

// ---------------------------------------------------------------------------
// flag_compact: token-driven dedup + warp-aggregated slot assignment.
// ---------------------------------------------------------------------------
__global__ __launch_bounds__(512) void flag_compact(const int* __restrict__ words) {
    const int tid = threadIdx.x, lane = tid & 31;
    const int w = words[blockIdx.x * 512 + tid];
    const int isnew = (atomicExch(&g_flags[w], 1) == 0);
    unsigned mask = __ballot_sync(0xffffffffu, isnew);
    int n = __popc(mask);
    int base = 0;
    if (lane == 0 && n) base = atomicAdd(&g_count, n);
    base = __shfl_sync(0xffffffffu, base, 0);
    if (isnew) {
        int slot = base + __popc(mask & ((1u << lane) - 1));
        g_slot[w] = slot;
        g_wlist[slot] = w;
    }
}

// ---------------------------------------------------------------------------
// gemm_z: Z[slot, 256] = embed[wlist[slot]] @ W1emb^T via int8 IMMA.
// ---------------------------------------------------------------------------
#define GST    12
#define GSTAGE 3840
#define GBOFF  768

__global__ __launch_bounds__(256, 2) void gemm_z(const float* __restrict__ embed_w) {
    __shared__ unsigned S[2 * GSTAGE];

    const int m0 = blockIdx.x * 64;
    const int padded = (g_count + 63) & ~63;
    if (m0 >= padded) return;

    const int tid  = threadIdx.x;
    const int warp = tid >> 5, lane = tid & 31;
    const int wm = warp >> 2, wn = warp & 3;
    const int gr = lane >> 2, tc = lane & 3;

    const int aR = tid >> 2, aQ = tid & 3;
    const float* aSrc = embed_w + (long)__ldg(g_wlist + m0 + aR) * EMB + aQ * 8;
    const uint4* bSrc = (const uint4*)g_fc1i8 + tid * 2;

    const int aDst = aR * GST + aQ * 2;
    const int bDst = GBOFF + tid * GST;

    int acc[2][8][4];
#pragma unroll
    for (int mi = 0; mi < 2; mi++)
#pragma unroll
        for (int nj = 0; nj < 8; nj++)
#pragma unroll
            for (int q = 0; q < 4; q++) acc[mi][nj][q] = 0;

    float4 aV0 = *(const float4*)(aSrc);
    float4 aV1 = *(const float4*)(aSrc + 4);
    uint4  bV0 = *(bSrc);
    uint4  bV1 = *(bSrc + 1);
    {
        uint2 o;
        o.x = pack_s8x4(q8(aV0.x), q8(aV0.y), q8(aV0.z), q8(aV0.w));
        o.y = pack_s8x4(q8(aV1.x), q8(aV1.y), q8(aV1.z), q8(aV1.w));
        *(uint2*)(S + aDst) = o;
        *(uint4*)(S + bDst) = bV0;
        *(uint4*)(S + bDst + 4) = bV1;
    }
    __syncthreads();

    const int r0a = wm * 32 + gr;
    const int n0  = wn * 64 + gr;

#pragma unroll 2
    for (int it = 0; it < 24; ++it) {
        unsigned* cur = S + (it & 1) * GSTAGE;

        if (it + 1 < 24) {
            const float* ap = aSrc + (it + 1) * 32;
            aV0 = *(const float4*)(ap);
            aV1 = *(const float4*)(ap + 4);
            const uint4* bp = bSrc + (it + 1) * 512;
            bV0 = *(bp);
            bV1 = *(bp + 1);
        }

        unsigned a[2][4];
#pragma unroll
        for (int mi = 0; mi < 2; mi++) {
            int r0 = r0a + mi * 16;
            a[mi][0] = cur[r0 * GST + tc];
            a[mi][1] = cur[(r0 + 8) * GST + tc];
            a[mi][2] = cur[r0 * GST + tc + 4];
            a[mi][3] = cur[(r0 + 8) * GST + tc + 4];
        }
#pragma unroll
        for (int nj = 0; nj < 8; nj++) {
            int n = n0 + nj * 8;
            unsigned b0 = cur[GBOFF + n * GST + tc];
            unsigned b1 = cur[GBOFF + n * GST + tc + 4];
            imma32(acc[0][nj], a[0], b0, b1);
            imma32(acc[1][nj], a[1], b0, b1);
        }

        if (it + 1 < 24) {
            unsigned* nxt = S + ((it + 1) & 1) * GSTAGE;
            uint2 o;
            o.x = pack_s8x4(q8(aV0.x), q8(aV0.y), q8(aV0.z), q8(aV0.w));
            o.y = pack_s8x4(q8(aV1.x), q8(aV1.y), q8(aV1.z), q8(aV1.w));
            *(uint2*)(nxt + aDst) = o;
            *(uint4*)(nxt + bDst) = bV0;
            *(uint4*)(nxt + bDst + 4) = bV1;
        }
        __syncthreads();
    }

#pragma unroll
    for (int mi = 0; mi < 2; mi++)
#pragma unroll
        for (int half = 0; half < 2; half++) {
            int row = wm * 32 + mi * 16 + half * 8 + gr;
#pragma unroll
            for (int nj = 0; nj < 8; nj++) {
                int col = wn * 64 + nj * 8 + tc * 2;
                float2 z;
                z.x = (float)acc[mi][nj][half * 2 + 0] * IQS2;
                z.y = (float)acc[mi][nj][half * 2 + 1] * IQS2;
                *(float2*)(g_Z + (long)(m0 + row) * HID + col) = z;
            }
        }
}

// ---------------------------------------------------------------------------
// tok_kernel v3: warp-per-token, 8 tokens/warp. Lane owns 8 cols (no smem).
// Tag-splitting butterfly reduction: 9 shfls to lane-distributed tag sums,
// then 6-shfl softmax over tags (lanes differ in bits 2,3,4).
// grid 512, block 256 (8 warps -> 4096 warps x 8 tokens).
// ---------------------------------------------------------------------------
__global__ __launch_bounds__(256, 2) void tok_kernel(
    const int* __restrict__ words,
    const int* __restrict__ corpus,
    const float* __restrict__ fc2_w,
    const float* __restrict__ fc2_b) {

    const int tid = threadIdx.x, wid = tid >> 5, lane = tid & 31;
    const int gw = blockIdx.x * 8 + wid;          // 0..4095
    const int tok0 = gw * 8;
    const int b = tok0 >> 9;
    const int cix = __ldg(corpus + b);
    const unsigned FULL = 0xffffffffu;

    // lane's 8 columns: lane*8 .. lane*8+7
    float d[8];
    {
        float4 u0 = __ldg((const float4*)(g_ctr10 + cix * HID + lane * 8));
        float4 u1 = __ldg((const float4*)(g_ctr10 + cix * HID + lane * 8 + 4));
        d[0] = u0.x; d[1] = u0.y; d[2] = u0.z; d[3] = u0.w;
        d[4] = u1.x; d[5] = u1.y; d[6] = u1.z; d[7] = u1.w;
    }
    float w2[NTAGS][8];
#pragma unroll
    for (int t = 0; t < NTAGS; t++) {
        float4 u0 = __ldg((const float4*)(fc2_w + t * HID + lane * 8));
        float4 u1 = __ldg((const float4*)(fc2_w + t * HID + lane * 8 + 4));
        w2[t][0] = u0.x; w2[t][1] = u0.y; w2[t][2] = u0.z; w2[t][3] = u0.w;
        w2[t][4] = u1.x; w2[t][5] = u1.y; w2[t][6] = u1.z; w2[t][7] = u1.w;
    }
    // this lane's final tag after the butterfly
    const int tag = ((lane >> 4) & 1) * 4 + ((lane >> 3) & 1) * 2 + ((lane >> 2) & 1);
    const float fbt = __ldg(fc2_b + tag);

    int sl[8];
#pragma unroll
    for (int k = 0; k < 8; k++)
        sl[k] = __ldg(g_slot + __ldg(words + tok0 + k));

    for (int k = 0; k < 8; k++) {
        const float* zr = g_Z + (long)sl[k] * HID + lane * 8;
        float4 z0 = __ldg((const float4*)(zr));
        float4 z1 = __ldg((const float4*)(zr + 4));
        float h[8];
        h[0] = fmaxf(z0.x + d[0], 0.f); h[1] = fmaxf(z0.y + d[1], 0.f);
        h[2] = fmaxf(z0.z + d[2], 0.f); h[3] = fmaxf(z0.w + d[3], 0.f);
        h[4] = fmaxf(z1.x + d[4], 0.f); h[5] = fmaxf(z1.y + d[5], 0.f);
        h[6] = fmaxf(z1.z + d[6], 0.f); h[7] = fmaxf(z1.w + d[7], 0.f);

        float p[NTAGS];
#pragma unroll
        for (int t = 0; t < NTAGS; t++) {
            float s = 0.f;
#pragma unroll
            for (int q = 0; q < 8; q++) s = fmaf(h[q], w2[t][q], s);
            p[t] = s;
        }

        // --- tag-splitting butterfly: 9 shfls ---
        // level A (xor 16): keep tags 0-3 (bit16=0) or 4-7 (bit16=1)
#pragma unroll
        for (int i = 0; i < 4; i++) {
            float send = (lane & 16) ? p[i] : p[i + 4];
            float r = __shfl_xor_sync(FULL, send, 16);
            p[i] = ((lane & 16) ? p[i + 4] : p[i]) + r;
        }
        // level B (xor 8): keep sub-tags 0-1 or 2-3
#pragma unroll
        for (int i = 0; i < 2; i++) {
            float send = (lane & 8) ? p[i] : p[i + 2];
            float r = __shfl_xor_sync(FULL, send, 8);
            p[i] = ((lane & 8) ? p[i + 2] : p[i]) + r;
        }
        // level C (xor 4): keep sub-tag 0 or 1
        float v;
        {
            float send = (lane & 4) ? p[0] : p[1];
            float r = __shfl_xor_sync(FULL, send, 4);
            v = ((lane & 4) ? p[1] : p[0]) + r;
        }
        // level D: fold the 4 same-tag lanes (bits 0,1)
        v += __shfl_xor_sync(FULL, v, 1);
        v += __shfl_xor_sync(FULL, v, 2);
        v += fbt;

        // --- softmax over tags (lanes differing in bits 2,3,4) ---
        float mx = v;
        mx = fmaxf(mx, __shfl_xor_sync(FULL, mx, 4));
        mx = fmaxf(mx, __shfl_xor_sync(FULL, mx, 8));
        mx = fmaxf(mx, __shfl_xor_sync(FULL, mx, 16));
        float sm = __expf(v - mx);
        sm += __shfl_xor_sync(FULL, sm, 4);
        sm += __shfl_xor_sync(FULL, sm, 8);
        sm += __shfl_xor_sync(FULL, sm, 16);
        float lse = mx + __logf(sm);

        if ((lane & 3) == 0)
            g_logits[(long)(tok0 + k) * NTAGS + tag] = v - lse;
    }
}

// ---------------------------------------------------------------------------
// crf_chunk: CLEN=16-step operator matrix per block. grid 2048, block 64.
// ---------------------------------------------------------------------------
__global__ __launch_bounds__(64) void crf_chunk(
    const int* __restrict__ words,
    const float* __restrict__ trans) {

    __shared__ float sL[CLEN * NTAGS];
    __shared__ int   sW[CLEN];

    const int b = blockIdx.x >> 5, chunk = blockIdx.x & 31;
    const int tid = threadIdx.x;
    const int j = tid & 7;
    const int lane = tid & 31, rowBase = lane & ~7;

    const float* L = g_logits + b * SEQ * NTAGS + chunk * CLEN * NTAGS;
    const int* wds = words + b * SEQ + chunk * CLEN;

    if (tid < 32) *(float4*)&sL[tid * 4] = *(const float4*)(L + tid * 4);
    if (tid < CLEN) sW[tid] = wds[tid];

    float tcol[8];
#pragma unroll
    for (int k = 0; k < 8; k++) tcol[k] = __ldg(trans + k * NTAGS + j);

    __syncthreads();

    float M = ((tid >> 3) == j) ? 0.f : -1e30f;
    const int skip0 = (chunk == 0);

#pragma unroll
    for (int s = 0; s < CLEN; s++) {
        float emit = sL[s * NTAGS + j];
        int live = (sW[s] != 0) & ((s > 0) | !skip0);
        float v[8];
#pragma unroll
        for (int k = 0; k < 8; k++)
            v[k] = __shfl_sync(0xffffffffu, M, rowBase + k) + tcol[k];
        float m01 = fmaxf(v[0], v[1]), m23 = fmaxf(v[2], v[3]);
        float m45 = fmaxf(v[4], v[5]), m67 = fmaxf(v[6], v[7]);
        float mx  = fmaxf(fmaxf(m01, m23), fmaxf(m45, m67));
        float s0 = __expf(v[0] - mx) + __expf(v[1] - mx);
        float s1 = __expf(v[2] - mx) + __expf(v[3] - mx);
        float s2 = __expf(v[4] - mx) + __expf(v[5] - mx);
        float s3 = __expf(v[6] - mx) + __expf(v[7] - mx);
        float nv = mx + __logf((s0 + s1) + (s2 + s3)) + emit;
        M = live ? nv : M;
    }
    g_crfM[blockIdx.x * 64 + tid] = M;
}

// ---------------------------------------------------------------------------
// crf_fin: combine 32 chunk matrices + norm + gold score. grid 64, block 512.
// ---------------------------------------------------------------------------
__global__ __launch_bounds__(512) void crf_fin(
    const int* __restrict__ words,
    const int* __restrict__ target,
    const float* __restrict__ trans,
    const float* __restrict__ start_s,
    const float* __restrict__ end_s,
    float* __restrict__ out) {

    __shared__ float sM[NCHUNK * 64];
    __shared__ float sRed[16];
    __shared__ int   sRedI[16];
    __shared__ float sNorm;

    const int b = blockIdx.x, tid = threadIdx.x;
    const int lane = tid & 31;
    const float* L = g_logits + b * SEQ * NTAGS;
    const int* wds = words + b * SEQ;
    const int* tg  = target + b * SEQ;

#pragma unroll
    for (int k = 0; k < 4; k++) sM[tid + k * 512] = g_crfM[b * (NCHUNK * 64) + tid + k * 512];
    __syncthreads();

    if (tid < 8) {
        float alpha = __ldg(L + tid) + __ldg(start_s + tid);
#pragma unroll
        for (int c = 0; c < NCHUNK; c++) {
            float v[8];
#pragma unroll
            for (int k = 0; k < 8; k++)
                v[k] = __shfl_sync(0xffu, alpha, k) + sM[c * 64 + k * 8 + tid];
            float m01 = fmaxf(v[0], v[1]), m23 = fmaxf(v[2], v[3]);
            float m45 = fmaxf(v[4], v[5]), m67 = fmaxf(v[6], v[7]);
            float mx  = fmaxf(fmaxf(m01, m23), fmaxf(m45, m67));
            float sm = __expf(v[0] - mx) + __expf(v[1] - mx) + __expf(v[2] - mx)
                     + __expf(v[3] - mx) + __expf(v[4] - mx) + __expf(v[5] - mx)
                     + __expf(v[6] - mx) + __expf(v[7] - mx);
            alpha = mx + __logf(sm);
        }
        float v = alpha + __ldg(end_s + tid);
        float mx = v;
        mx = fmaxf(mx, __shfl_xor_sync(0xffu, mx, 1));
        mx = fmaxf(mx, __shfl_xor_sync(0xffu, mx, 2));
        mx = fmaxf(mx, __shfl_xor_sync(0xffu, mx, 4));
        float sm = __expf(v - mx);
        sm += __shfl_xor_sync(0xffu, sm, 1);
        sm += __shfl_xor_sync(0xffu, sm, 2);
        sm += __shfl_xor_sync(0xffu, sm, 4);
        if (tid == 0) sNorm = mx + __logf(sm);
    }

    {
        const int s = tid;
        int m = (wds[s] != 0);
        int t = tg[s];
        float e  = m ? __ldg(L + s * NTAGS + t) : 0.f;
        float tr = (m && s > 0) ? __ldg(trans + tg[s - 1] * NTAGS + t) : 0.f;
        float val = e + tr;
        int cnt = m;
#pragma unroll
        for (int off = 16; off > 0; off >>= 1) {
            val += __shfl_down_sync(0xffffffffu, val, off);
            cnt += __shfl_down_sync(0xffffffffu, cnt, off);
        }
        if (lane == 0) { sRed[tid >> 5] = val; sRedI[tid >> 5] = cnt; }
    }
    __syncthreads();
    if (tid == 0) {
        float sum = 0.f; int c = 0;
#pragma unroll
        for (int w = 0; w < 16; w++) { sum += sRed[w]; c += sRedI[w]; }
        int last = c - 1;
        float score = sum + __ldg(start_s + tg[0]) + __ldg(end_s + tg[last]);
        out[b] = sNorm - score;
    }
}

// ---------------------------------------------------------------------------
extern "C" void kernel_launch(void* const* d_in, const int* in_sizes, int n_in,
                              void* d_out, int out_size) {
    const int*   words   = (const int*)  d_in[0];
    const int*   target  = (const int*)  d_in[1];
    const int*   corpus  = (const int*)  d_in[2];
    const float* embed_w = (const float*)d_in[3];
    const float* dom_w   = (const float*)d_in[4];
    const float* fc1_w   = (const float*)d_in[5];
    const float* fc1_b   = (const float*)d_in[6];
    const float* fc2_w   = (const float*)d_in[7];
    const float* fc2_b   = (const float*)d_in[8];
    const float* trans   = (const float*)d_in[9];
    const float* start_s = (const float*)d_in[10];
    const float* end_s   = (const float*)d_in[11];
    float* out = (float*)d_out;

    prep_all<<<190, 256>>>(fc1_w, dom_w, fc1_b);
    flag_compact<<<64, 512>>>(words);
    gemm_z<<<332, 256>>>(embed_w);
    tok_kernel<<<512, 256>>>(words, corpus, fc2_w, fc2_b);
    crf_chunk<<<BATCH * NCHUNK, 64>>>(words, trans);
    crf_fin<<<BATCH, 512>>>(words, target, trans, start_s, end_s, out);
}

// round 15
// speedup vs baseline: 1.1960x; 1.0227x over previous
#include <cuda_runtime.h>
#include <cstdint>

#define VOCAB 21128
#define EMB   768
#define HID   256
#define NTAGS 8
#define BATCH 64
#define SEQ   512
#define NTOK  (BATCH * SEQ)
#define NCORP 10
#define NCHUNK 32
#define CLEN   16

#define ZROWS  21248                  // vocab padded to 332*64
#define QS     1024.0f
#define IQS2   9.5367431640625e-07f   // 1 / (1024*1024)

// ---------------- scratch (device globals; no allocs allowed) ----------------
__device__ float g_logits[NTOK * NTAGS];
__device__ float g_ctr10[NCORP * HID];
__device__ __align__(16) unsigned g_fc1i8[24 * 2048];  // fc1_w s8*1024, [ks][n][8w]
__device__ float g_Z[ZROWS * HID];
__device__ float g_crfM[BATCH * NCHUNK * 64];
__device__ int   g_flags[VOCAB];
__device__ int   g_slot[VOCAB];
__device__ int   g_wlist[ZROWS];
__device__ int   g_count;

// ---------------------------------------------------------------------------
__device__ __forceinline__ unsigned pack_s8x4(int x0, int x1, int x2, int x3) {
    unsigned t, r, z = 0;
    asm("cvt.pack.sat.s8.s32.b32 %0, %1, %2, %3;" : "=r"(t) : "r"(x3), "r"(x2), "r"(z));
    asm("cvt.pack.sat.s8.s32.b32 %0, %1, %2, %3;" : "=r"(r) : "r"(x1), "r"(x0), "r"(t));
    return r;
}
__device__ __forceinline__ int q8(float x) { return __float2int_rn(x * QS); }

__device__ __forceinline__ void imma32(int* c, const unsigned* a, unsigned b0, unsigned b1) {
    asm volatile(
        "mma.sync.aligned.m16n8k32.row.col.s32.s8.s8.s32 "
        "{%0,%1,%2,%3},{%4,%5,%6,%7},{%8,%9},{%0,%1,%2,%3};"
        : "+r"(c[0]), "+r"(c[1]), "+r"(c[2]), "+r"(c[3])
        : "r"(a[0]), "r"(a[1]), "r"(a[2]), "r"(a[3]), "r"(b0), "r"(b1));
}

// ---------------------------------------------------------------------------
// prep_all: fused weight-quant + domain-ctr + metadata zeroing.
// blocks [0,96): fc1i8; [96,106): ctr; [106,190): zero flags/wlist/count.
// ---------------------------------------------------------------------------
__global__ __launch_bounds__(256) void prep_all(
    const float* __restrict__ fc1_w,
    const float* __restrict__ dom_w,
    const float* __restrict__ fc1_b) {

    __shared__ float sDom[HID];
    const int bx = blockIdx.x, tid = threadIdx.x;

    if (bx < 96) {
        int id = bx * 256 + tid;
        int ks = id >> 10, rem = id & 1023;
        int n = rem >> 2, q = rem & 3;
        const float* src = fc1_w + n * (HID + EMB) + ks * 32 + q * 8;
        float4 v0 = *(const float4*)(src);
        float4 v1 = *(const float4*)(src + 4);
        uint2 o;
        o.x = pack_s8x4(q8(v0.x), q8(v0.y), q8(v0.z), q8(v0.w));
        o.y = pack_s8x4(q8(v1.x), q8(v1.y), q8(v1.z), q8(v1.w));
        ((uint2*)g_fc1i8)[ks * 1024 + n * 4 + q] = o;
    } else if (bx < 106) {
        const int c = bx - 96;
        sDom[tid] = dom_w[c * HID + tid];
        __syncthreads();
        const int w = tid >> 5, lane = tid & 31;
        for (int n = w; n < HID; n += 8) {
            const float* row = fc1_w + n * (HID + EMB) + EMB;
            float4 x0 = *(const float4*)(row + lane * 4);
            float4 x1 = *(const float4*)(row + 128 + lane * 4);
            float4 d0 = *(const float4*)(sDom + lane * 4);
            float4 d1 = *(const float4*)(sDom + 128 + lane * 4);
            float acc = x0.x * d0.x + x0.y * d0.y + x0.z * d0.z + x0.w * d0.w
                      + x1.x * d1.x + x1.y * d1.y + x1.z * d1.z + x1.w * d1.w;
#pragma unroll
            for (int off = 16; off > 0; off >>= 1)
                acc += __shfl_down_sync(0xffffffffu, acc, off);
            if (lane == 0) g_ctr10[c * HID + n] = acc + fc1_b[n];
        }
    } else {
        int i = (bx - 106) * 256 + tid;
        if (i < VOCAB) g_flags[i] = 0;
        if (i < ZROWS) g_wlist[i] = 0;
        if (i == 0) g_count = 0;
    }
}

// ---------------------------------------------------------------------------
// flag_compact: token-driven dedup + warp-aggregated slot assignment.
// ---------------------------------------------------------------------------
__global__ __launch_bounds__(512) void flag_compact(const int* __restrict__ words) {
    const int tid = threadIdx.x, lane = tid & 31;
    const int w = words[blockIdx.x * 512 + tid];
    const int isnew = (atomicExch(&g_flags[w], 1) == 0);
    unsigned mask = __ballot_sync(0xffffffffu, isnew);
    int n = __popc(mask);
    int base = 0;
    if (lane == 0 && n) base = atomicAdd(&g_count, n);
    base = __shfl_sync(0xffffffffu, base, 0);
    if (isnew) {
        int slot = base + __popc(mask & ((1u << lane) - 1));
        g_slot[w] = slot;
        g_wlist[slot] = w;
    }
}

// ---------------------------------------------------------------------------
// gemm_z: Z[slot, 256] = embed[wlist[slot]] @ W1emb^T via int8 IMMA.
// ---------------------------------------------------------------------------
#define GST    12
#define GSTAGE 3840
#define GBOFF  768

__global__ __launch_bounds__(256, 2) void gemm_z(const float* __restrict__ embed_w) {
    __shared__ unsigned S[2 * GSTAGE];

    const int m0 = blockIdx.x * 64;
    const int padded = (g_count + 63) & ~63;
    if (m0 >= padded) return;

    const int tid  = threadIdx.x;
    const int warp = tid >> 5, lane = tid & 31;
    const int wm = warp >> 2, wn = warp & 3;
    const int gr = lane >> 2, tc = lane & 3;

    const int aR = tid >> 2, aQ = tid & 3;
    const float* aSrc = embed_w + (long)__ldg(g_wlist + m0 + aR) * EMB + aQ * 8;
    const uint4* bSrc = (const uint4*)g_fc1i8 + tid * 2;

    const int aDst = aR * GST + aQ * 2;
    const int bDst = GBOFF + tid * GST;

    int acc[2][8][4];
#pragma unroll
    for (int mi = 0; mi < 2; mi++)
#pragma unroll
        for (int nj = 0; nj < 8; nj++)
#pragma unroll
            for (int q = 0; q < 4; q++) acc[mi][nj][q] = 0;

    float4 aV0 = *(const float4*)(aSrc);
    float4 aV1 = *(const float4*)(aSrc + 4);
    uint4  bV0 = *(bSrc);
    uint4  bV1 = *(bSrc + 1);
    {
        uint2 o;
        o.x = pack_s8x4(q8(aV0.x), q8(aV0.y), q8(aV0.z), q8(aV0.w));
        o.y = pack_s8x4(q8(aV1.x), q8(aV1.y), q8(aV1.z), q8(aV1.w));
        *(uint2*)(S + aDst) = o;
        *(uint4*)(S + bDst) = bV0;
        *(uint4*)(S + bDst + 4) = bV1;
    }
    __syncthreads();

    const int r0a = wm * 32 + gr;
    const int n0  = wn * 64 + gr;

#pragma unroll 2
    for (int it = 0; it < 24; ++it) {
        unsigned* cur = S + (it & 1) * GSTAGE;

        if (it + 1 < 24) {
            const float* ap = aSrc + (it + 1) * 32;
            aV0 = *(const float4*)(ap);
            aV1 = *(const float4*)(ap + 4);
            const uint4* bp = bSrc + (it + 1) * 512;
            bV0 = *(bp);
            bV1 = *(bp + 1);
        }

        unsigned a[2][4];
#pragma unroll
        for (int mi = 0; mi < 2; mi++) {
            int r0 = r0a + mi * 16;
            a[mi][0] = cur[r0 * GST + tc];
            a[mi][1] = cur[(r0 + 8) * GST + tc];
            a[mi][2] = cur[r0 * GST + tc + 4];
            a[mi][3] = cur[(r0 + 8) * GST + tc + 4];
        }
#pragma unroll
        for (int nj = 0; nj < 8; nj++) {
            int n = n0 + nj * 8;
            unsigned b0 = cur[GBOFF + n * GST + tc];
            unsigned b1 = cur[GBOFF + n * GST + tc + 4];
            imma32(acc[0][nj], a[0], b0, b1);
            imma32(acc[1][nj], a[1], b0, b1);
        }

        if (it + 1 < 24) {
            unsigned* nxt = S + ((it + 1) & 1) * GSTAGE;
            uint2 o;
            o.x = pack_s8x4(q8(aV0.x), q8(aV0.y), q8(aV0.z), q8(aV0.w));
            o.y = pack_s8x4(q8(aV1.x), q8(aV1.y), q8(aV1.z), q8(aV1.w));
            *(uint2*)(nxt + aDst) = o;
            *(uint4*)(nxt + bDst) = bV0;
            *(uint4*)(nxt + bDst + 4) = bV1;
        }
        __syncthreads();
    }

#pragma unroll
    for (int mi = 0; mi < 2; mi++)
#pragma unroll
        for (int half = 0; half < 2; half++) {
            int row = wm * 32 + mi * 16 + half * 8 + gr;
#pragma unroll
            for (int nj = 0; nj < 8; nj++) {
                int col = wn * 64 + nj * 8 + tc * 2;
                float2 z;
                z.x = (float)acc[mi][nj][half * 2 + 0] * IQS2;
                z.y = (float)acc[mi][nj][half * 2 + 1] * IQS2;
                *(float2*)(g_Z + (long)(m0 + row) * HID + col) = z;
            }
        }
}

// ---------------------------------------------------------------------------
// tok_kernel v4: warp-per-token, 4 tokens/warp, ALL Z loads front-batched
// (MLP=8/warp). Tag-splitting butterfly reduction (9 shfls) + 6-shfl softmax.
// grid 1024, block 256 (8 warps -> 8192 warps x 4 tokens).
// ---------------------------------------------------------------------------
__global__ __launch_bounds__(256, 2) void tok_kernel(
    const int* __restrict__ words,
    const int* __restrict__ corpus,
    const float* __restrict__ fc2_w,
    const float* __restrict__ fc2_b) {

    const int tid = threadIdx.x, wid = tid >> 5, lane = tid & 31;
    const int gw = blockIdx.x * 8 + wid;          // 0..8191
    const int tok0 = gw * 4;
    const int b = tok0 >> 9;
    const int cix = __ldg(corpus + b);
    const unsigned FULL = 0xffffffffu;

    // lane's 8 columns: lane*8 .. lane*8+7
    float d[8];
    {
        float4 u0 = __ldg((const float4*)(g_ctr10 + cix * HID + lane * 8));
        float4 u1 = __ldg((const float4*)(g_ctr10 + cix * HID + lane * 8 + 4));
        d[0] = u0.x; d[1] = u0.y; d[2] = u0.z; d[3] = u0.w;
        d[4] = u1.x; d[5] = u1.y; d[6] = u1.z; d[7] = u1.w;
    }
    float w2[NTAGS][8];
#pragma unroll
    for (int t = 0; t < NTAGS; t++) {
        float4 u0 = __ldg((const float4*)(fc2_w + t * HID + lane * 8));
        float4 u1 = __ldg((const float4*)(fc2_w + t * HID + lane * 8 + 4));
        w2[t][0] = u0.x; w2[t][1] = u0.y; w2[t][2] = u0.z; w2[t][3] = u0.w;
        w2[t][4] = u1.x; w2[t][5] = u1.y; w2[t][6] = u1.z; w2[t][7] = u1.w;
    }
    const int tag = ((lane >> 4) & 1) * 4 + ((lane >> 3) & 1) * 2 + ((lane >> 2) & 1);
    const float fbt = __ldg(fc2_b + tag);

    // front-batch ALL Z loads: 4 tokens x 2 float4s
    int sl[4];
#pragma unroll
    for (int k = 0; k < 4; k++)
        sl[k] = __ldg(g_slot + __ldg(words + tok0 + k));
    float4 zz[4][2];
#pragma unroll
    for (int k = 0; k < 4; k++) {
        const float* zr = g_Z + (long)sl[k] * HID + lane * 8;
        zz[k][0] = __ldg((const float4*)(zr));
        zz[k][1] = __ldg((const float4*)(zr + 4));
    }

#pragma unroll
    for (int k = 0; k < 4; k++) {
        float h[8];
        h[0] = fmaxf(zz[k][0].x + d[0], 0.f); h[1] = fmaxf(zz[k][0].y + d[1], 0.f);
        h[2] = fmaxf(zz[k][0].z + d[2], 0.f); h[3] = fmaxf(zz[k][0].w + d[3], 0.f);
        h[4] = fmaxf(zz[k][1].x + d[4], 0.f); h[5] = fmaxf(zz[k][1].y + d[5], 0.f);
        h[6] = fmaxf(zz[k][1].z + d[6], 0.f); h[7] = fmaxf(zz[k][1].w + d[7], 0.f);

        float p[NTAGS];
#pragma unroll
        for (int t = 0; t < NTAGS; t++) {
            float s = 0.f;
#pragma unroll
            for (int q = 0; q < 8; q++) s = fmaf(h[q], w2[t][q], s);
            p[t] = s;
        }

        // --- tag-splitting butterfly: 9 shfls ---
#pragma unroll
        for (int i = 0; i < 4; i++) {
            float send = (lane & 16) ? p[i] : p[i + 4];
            float r = __shfl_xor_sync(FULL, send, 16);
            p[i] = ((lane & 16) ? p[i + 4] : p[i]) + r;
        }
#pragma unroll
        for (int i = 0; i < 2; i++) {
            float send = (lane & 8) ? p[i] : p[i + 2];
            float r = __shfl_xor_sync(FULL, send, 8);
            p[i] = ((lane & 8) ? p[i + 2] : p[i]) + r;
        }
        float v;
        {
            float send = (lane & 4) ? p[0] : p[1];
            float r = __shfl_xor_sync(FULL, send, 4);
            v = ((lane & 4) ? p[1] : p[0]) + r;
        }
        v += __shfl_xor_sync(FULL, v, 1);
        v += __shfl_xor_sync(FULL, v, 2);
        v += fbt;

        // --- softmax over tags (lanes differing in bits 2,3,4) ---
        float mx = v;
        mx = fmaxf(mx, __shfl_xor_sync(FULL, mx, 4));
        mx = fmaxf(mx, __shfl_xor_sync(FULL, mx, 8));
        mx = fmaxf(mx, __shfl_xor_sync(FULL, mx, 16));
        float sm = __expf(v - mx);
        sm += __shfl_xor_sync(FULL, sm, 4);
        sm += __shfl_xor_sync(FULL, sm, 8);
        sm += __shfl_xor_sync(FULL, sm, 16);
        float lse = mx + __logf(sm);

        if ((lane & 3) == 0)
            g_logits[(long)(tok0 + k) * NTAGS + tag] = v - lse;
    }
}

// ---------------------------------------------------------------------------
// crf_chunk: CLEN=16-step operator matrix per block. grid 2048, block 64.
// ---------------------------------------------------------------------------
__global__ __launch_bounds__(64) void crf_chunk(
    const int* __restrict__ words,
    const float* __restrict__ trans) {

    __shared__ float sL[CLEN * NTAGS];
    __shared__ int   sW[CLEN];

    const int b = blockIdx.x >> 5, chunk = blockIdx.x & 31;
    const int tid = threadIdx.x;
    const int j = tid & 7;
    const int lane = tid & 31, rowBase = lane & ~7;

    const float* L = g_logits + b * SEQ * NTAGS + chunk * CLEN * NTAGS;
    const int* wds = words + b * SEQ + chunk * CLEN;

    if (tid < 32) *(float4*)&sL[tid * 4] = *(const float4*)(L + tid * 4);
    if (tid < CLEN) sW[tid] = wds[tid];

    float tcol[8];
#pragma unroll
    for (int k = 0; k < 8; k++) tcol[k] = __ldg(trans + k * NTAGS + j);

    __syncthreads();

    float M = ((tid >> 3) == j) ? 0.f : -1e30f;
    const int skip0 = (chunk == 0);

#pragma unroll
    for (int s = 0; s < CLEN; s++) {
        float emit = sL[s * NTAGS + j];
        int live = (sW[s] != 0) & ((s > 0) | !skip0);
        float v[8];
#pragma unroll
        for (int k = 0; k < 8; k++)
            v[k] = __shfl_sync(0xffffffffu, M, rowBase + k) + tcol[k];
        float m01 = fmaxf(v[0], v[1]), m23 = fmaxf(v[2], v[3]);
        float m45 = fmaxf(v[4], v[5]), m67 = fmaxf(v[6], v[7]);
        float mx  = fmaxf(fmaxf(m01, m23), fmaxf(m45, m67));
        float s0 = __expf(v[0] - mx) + __expf(v[1] - mx);
        float s1 = __expf(v[2] - mx) + __expf(v[3] - mx);
        float s2 = __expf(v[4] - mx) + __expf(v[5] - mx);
        float s3 = __expf(v[6] - mx) + __expf(v[7] - mx);
        float nv = mx + __logf((s0 + s1) + (s2 + s3)) + emit;
        M = live ? nv : M;
    }
    g_crfM[blockIdx.x * 64 + tid] = M;
}

// ---------------------------------------------------------------------------
// crf_fin: combine 32 chunk matrices + norm + gold score. grid 64, block 512.
// ---------------------------------------------------------------------------
__global__ __launch_bounds__(512) void crf_fin(
    const int* __restrict__ words,
    const int* __restrict__ target,
    const float* __restrict__ trans,
    const float* __restrict__ start_s,
    const float* __restrict__ end_s,
    float* __restrict__ out) {

    __shared__ float sM[NCHUNK * 64];
    __shared__ float sRed[16];
    __shared__ int   sRedI[16];
    __shared__ float sNorm;

    const int b = blockIdx.x, tid = threadIdx.x;
    const int lane = tid & 31;
    const float* L = g_logits + b * SEQ * NTAGS;
    const int* wds = words + b * SEQ;
    const int* tg  = target + b * SEQ;

#pragma unroll
    for (int k = 0; k < 4; k++) sM[tid + k * 512] = g_crfM[b * (NCHUNK * 64) + tid + k * 512];
    __syncthreads();

    if (tid < 8) {
        float alpha = __ldg(L + tid) + __ldg(start_s + tid);
#pragma unroll
        for (int c = 0; c < NCHUNK; c++) {
            float v[8];
#pragma unroll
            for (int k = 0; k < 8; k++)
                v[k] = __shfl_sync(0xffu, alpha, k) + sM[c * 64 + k * 8 + tid];
            float m01 = fmaxf(v[0], v[1]), m23 = fmaxf(v[2], v[3]);
            float m45 = fmaxf(v[4], v[5]), m67 = fmaxf(v[6], v[7]);
            float mx  = fmaxf(fmaxf(m01, m23), fmaxf(m45, m67));
            float sm = __expf(v[0] - mx) + __expf(v[1] - mx) + __expf(v[2] - mx)
                     + __expf(v[3] - mx) + __expf(v[4] - mx) + __expf(v[5] - mx)
                     + __expf(v[6] - mx) + __expf(v[7] - mx);
            alpha = mx + __logf(sm);
        }
        float v = alpha + __ldg(end_s + tid);
        float mx = v;
        mx = fmaxf(mx, __shfl_xor_sync(0xffu, mx, 1));
        mx = fmaxf(mx, __shfl_xor_sync(0xffu, mx, 2));
        mx = fmaxf(mx, __shfl_xor_sync(0xffu, mx, 4));
        float sm = __expf(v - mx);
        sm += __shfl_xor_sync(0xffu, sm, 1);
        sm += __shfl_xor_sync(0xffu, sm, 2);
        sm += __shfl_xor_sync(0xffu, sm, 4);
        if (tid == 0) sNorm = mx + __logf(sm);
    }

    {
        const int s = tid;
        int m = (wds[s] != 0);
        int t = tg[s];
        float e  = m ? __ldg(L + s * NTAGS + t) : 0.f;
        float tr = (m && s > 0) ? __ldg(trans + tg[s - 1] * NTAGS + t) : 0.f;
        float val = e + tr;
        int cnt = m;
#pragma unroll
        for (int off = 16; off > 0; off >>= 1) {
            val += __shfl_down_sync(0xffffffffu, val, off);
            cnt += __shfl_down_sync(0xffffffffu, cnt, off);
        }
        if (lane == 0) { sRed[tid >> 5] = val; sRedI[tid >> 5] = cnt; }
    }
    __syncthreads();
    if (tid == 0) {
        float sum = 0.f; int c = 0;
#pragma unroll
        for (int w = 0; w < 16; w++) { sum += sRed[w]; c += sRedI[w]; }
        int last = c - 1;
        float score = sum + __ldg(start_s + tg[0]) + __ldg(end_s + tg[last]);
        out[b] = sNorm - score;
    }
}

// ---------------------------------------------------------------------------
extern "C" void kernel_launch(void* const* d_in, const int* in_sizes, int n_in,
                              void* d_out, int out_size) {
    const int*   words   = (const int*)  d_in[0];
    const int*   target  = (const int*)  d_in[1];
    const int*   corpus  = (const int*)  d_in[2];
    const float* embed_w = (const float*)d_in[3];
    const float* dom_w   = (const float*)d_in[4];
    const float* fc1_w   = (const float*)d_in[5];
    const float* fc1_b   = (const float*)d_in[6];
    const float* fc2_w   = (const float*)d_in[7];
    const float* fc2_b   = (const float*)d_in[8];
    const float* trans   = (const float*)d_in[9];
    const float* start_s = (const float*)d_in[10];
    const float* end_s   = (const float*)d_in[11];
    float* out = (float*)d_out;

    prep_all<<<190, 256>>>(fc1_w, dom_w, fc1_b);
    flag_compact<<<64, 512>>>(words);
    gemm_z<<<332, 256>>>(embed_w);
    tok_kernel<<<1024, 256>>>(words, corpus, fc2_w, fc2_b);
    crf_chunk<<<BATCH * NCHUNK, 64>>>(words, trans);
    crf_fin<<<BATCH, 512>>>(words, target, trans, start_s, end_s, out);
}